// round 1
// baseline (speedup 1.0000x reference)
#include <cuda_runtime.h>

#define N_NODES  200000
#define N_EDGES  3200000
#define N_PAIRS  4096
#define FEAT     32
#define CONCAT   128
#define SCAN_BLK 1024
#define NB_SCAN  196   // ceil(200000/1024)

// ---- scratch (device globals; no allocation allowed) ----
__device__ int   g_count[N_NODES];
__device__ int   g_offsets[N_NODES];
__device__ int   g_blocksums[256];
__device__ int   g_pos[N_EDGES];
__device__ int   g_adj[N_EDGES];
__device__ float g_invdeg[N_NODES];

// ---------------- CSR build ----------------
__global__ void hist_kernel(const int* __restrict__ dst) {
    int e = blockIdx.x * blockDim.x + threadIdx.x;
    if (e < N_EDGES) g_pos[e] = atomicAdd(&g_count[dst[e]], 1);
}

__global__ void scan_phase1() {
    __shared__ int s[SCAN_BLK];
    int i = blockIdx.x * SCAN_BLK + threadIdx.x;
    int v = (i < N_NODES) ? g_count[i] : 0;
    s[threadIdx.x] = v;
    __syncthreads();
    for (int d = 1; d < SCAN_BLK; d <<= 1) {
        int t = (threadIdx.x >= d) ? s[threadIdx.x - d] : 0;
        __syncthreads();
        if (threadIdx.x >= d) s[threadIdx.x] += t;
        __syncthreads();
    }
    if (i < N_NODES) g_offsets[i] = s[threadIdx.x] - v;   // exclusive
    if (threadIdx.x == SCAN_BLK - 1) g_blocksums[blockIdx.x] = s[SCAN_BLK - 1];
}

__global__ void scan_phase2(int nb) {
    __shared__ int s[256];
    int v = (threadIdx.x < nb) ? g_blocksums[threadIdx.x] : 0;
    s[threadIdx.x] = v;
    __syncthreads();
    for (int d = 1; d < 256; d <<= 1) {
        int t = (threadIdx.x >= d) ? s[threadIdx.x - d] : 0;
        __syncthreads();
        if (threadIdx.x >= d) s[threadIdx.x] += t;
        __syncthreads();
    }
    g_blocksums[threadIdx.x] = s[threadIdx.x] - v;        // exclusive
}

__global__ void scan_phase3() {
    int i = blockIdx.x * blockDim.x + threadIdx.x;
    if (i < N_NODES) g_offsets[i] += g_blocksums[i >> 10];
}

__global__ void invdeg_kernel() {
    int i = blockIdx.x * blockDim.x + threadIdx.x;
    if (i < N_NODES) g_invdeg[i] = 1.0f / fmaxf((float)g_count[i], 1.0f);
}

__global__ void fill_kernel(const int* __restrict__ src, const int* __restrict__ dst) {
    int e = blockIdx.x * blockDim.x + threadIdx.x;
    if (e < N_EDGES) g_adj[g_offsets[dst[e]] + g_pos[e]] = src[e];
}

// ---------------- fused SAGE layer ----------------
// warp per dst node; lane = feature. Gather+mean+matvec+tanh, write concat slice.
__global__ void layer_kernel(const float* __restrict__ hin, int stride,
                             float* __restrict__ hout,              // concat + l*32, row stride 128
                             const float* __restrict__ Ws,
                             const float* __restrict__ Wn,
                             const float* __restrict__ b) {
    __shared__ float sW[2 * 1024 + 32];
    int tid = threadIdx.x;
    for (int i = tid; i < 1024; i += blockDim.x) {
        sW[i] = Ws[i];
        sW[1024 + i] = Wn[i];
    }
    if (tid < 32) sW[2048 + tid] = b[tid];
    __syncthreads();

    int lane = tid & 31;
    int node = blockIdx.x * (blockDim.x >> 5) + (tid >> 5);
    if (node >= N_NODES) return;

    int beg = g_offsets[node];
    int cnt = g_count[node];
    int end = beg + cnt;

    float acc = 0.0f;
    for (int base = beg; base < end; base += 32) {
        int a = (base + lane < end) ? g_adj[base + lane] : 0;
        int m = end - base;
        if (m > 32) m = 32;
        for (int j = 0; j < m; j++) {
            int s = __shfl_sync(0xffffffffu, a, j);
            acc += __ldg(&hin[(size_t)s * stride + lane]);
        }
    }
    float mean = acc * g_invdeg[node];
    float hv   = __ldg(&hin[(size_t)node * stride + lane]);

    float o = sW[2048 + lane];
#pragma unroll
    for (int k = 0; k < 32; k++) {
        float hk = __shfl_sync(0xffffffffu, hv, k);
        float mk = __shfl_sync(0xffffffffu, mean, k);
        o += hk * sW[k * 32 + lane] + mk * sW[1024 + k * 32 + lane];
    }
    hout[(size_t)node * CONCAT + lane] = tanhf(o);
}

// ---------------- pair MLP ----------------
// 128 threads/block, 32 pairs/block. Thread j owns W1 column j (regs),
// pair features staged in shared; shared-atomic reduce for the W2 dot.
__global__ void mlp_kernel(const float* __restrict__ concat,
                           const int* __restrict__ user_idx,
                           const int* __restrict__ item_idx,
                           const float* __restrict__ W1,
                           const float* __restrict__ bl1,
                           const float* __restrict__ W2,
                           const float* __restrict__ bl2,
                           float* __restrict__ score) {
    const int PB = 32;
    __shared__ float sP[PB][256];
    __shared__ float sOut[PB];
    int tid = threadIdx.x;       // 0..127
    int p0  = blockIdx.x * PB;

    for (int idx = tid; idx < PB * 256; idx += 128) {
        int p = idx >> 8, k = idx & 255;
        int pair = p0 + p;
        int node = (k < 128) ? user_idx[pair] : item_idx[pair];
        sP[p][k] = concat[(size_t)node * 128 + (k & 127)];
    }
    if (tid < PB) sOut[tid] = 0.0f;
    __syncthreads();

    float acc[PB];
#pragma unroll
    for (int p = 0; p < PB; p++) acc[p] = 0.0f;

    for (int k = 0; k < 256; k++) {
        float w = W1[k * 128 + tid];
#pragma unroll
        for (int p = 0; p < PB; p++) acc[p] += sP[p][k] * w;
    }

    float bj = bl1[tid];
    float w2 = W2[tid];
#pragma unroll
    for (int p = 0; p < PB; p++) {
        float h = fmaxf(acc[p] + bj, 0.0f);
        atomicAdd(&sOut[p], h * w2);
    }
    __syncthreads();

    if (tid < PB) {
        float v = sOut[tid] + bl2[0];
        score[p0 + tid] = 1.0f / (1.0f + expf(-v));
    }
}

// ---------------- launch ----------------
extern "C" void kernel_launch(void* const* d_in, const int* in_sizes, int n_in,
                              void* d_out, int out_size) {
    const float* x        = (const float*)d_in[0];
    const int*   src      = (const int*)d_in[1];
    const int*   dst      = (const int*)d_in[2];
    const int*   user_idx = (const int*)d_in[3];
    const int*   item_idx = (const int*)d_in[4];
    const float* Ws[4]; const float* Wn[4]; const float* B[4];
    for (int l = 0; l < 4; l++) {
        Ws[l] = (const float*)d_in[5 + 3 * l];
        Wn[l] = (const float*)d_in[6 + 3 * l];
        B[l]  = (const float*)d_in[7 + 3 * l];
    }
    const float* W1  = (const float*)d_in[17];
    const float* bl1 = (const float*)d_in[18];
    const float* W2  = (const float*)d_in[19];
    const float* bl2 = (const float*)d_in[20];

    float* out    = (float*)d_out;
    float* score  = out;             // [N_PAIRS]
    float* concat = out + N_PAIRS;   // [N_NODES, 128]

    void* countPtr = nullptr;
    cudaGetSymbolAddress(&countPtr, g_count);
    cudaMemsetAsync(countPtr, 0, N_NODES * sizeof(int));

    hist_kernel<<<(N_EDGES + 255) / 256, 256>>>(dst);
    scan_phase1<<<NB_SCAN, SCAN_BLK>>>();
    scan_phase2<<<1, 256>>>(NB_SCAN);
    scan_phase3<<<(N_NODES + 255) / 256, 256>>>();
    invdeg_kernel<<<(N_NODES + 255) / 256, 256>>>();
    fill_kernel<<<(N_EDGES + 255) / 256, 256>>>(src, dst);

    const int WPB = 8;  // warps per block (256 threads)
    int lblocks = (N_NODES + WPB - 1) / WPB;
    layer_kernel<<<lblocks, 256>>>(x,            32,  concat + 0,  Ws[0], Wn[0], B[0]);
    layer_kernel<<<lblocks, 256>>>(concat + 0,   128, concat + 32, Ws[1], Wn[1], B[1]);
    layer_kernel<<<lblocks, 256>>>(concat + 32,  128, concat + 64, Ws[2], Wn[2], B[2]);
    layer_kernel<<<lblocks, 256>>>(concat + 64,  128, concat + 96, Ws[3], Wn[3], B[3]);

    mlp_kernel<<<N_PAIRS / 32, 128>>>(concat, user_idx, item_idx, W1, bl1, W2, bl2, score);
}

// round 2
// speedup vs baseline: 1.5486x; 1.5486x over previous
#include <cuda_runtime.h>

#define N_NODES  200000
#define N_EDGES  3200000
#define N_PAIRS  4096
#define FEAT     32
#define CONCAT   128
#define SCAN_BLK 1024
#define NB_SCAN  196   // ceil(200000/1024)

// ---- scratch (device globals; no allocation allowed) ----
__device__ int   g_count[N_NODES];
__device__ int   g_offsets[N_NODES];
__device__ int   g_blocksums[256];
__device__ int   g_pos[N_EDGES];
__device__ int   g_adj[N_EDGES];
__device__ float g_invdeg[N_NODES];

// ---------------- CSR build ----------------
__global__ void hist_kernel(const int* __restrict__ dst) {
    int e = blockIdx.x * blockDim.x + threadIdx.x;
    if (e < N_EDGES) g_pos[e] = atomicAdd(&g_count[dst[e]], 1);
}

__global__ void scan_phase1() {
    __shared__ int s[SCAN_BLK];
    int i = blockIdx.x * SCAN_BLK + threadIdx.x;
    int v = (i < N_NODES) ? g_count[i] : 0;
    s[threadIdx.x] = v;
    __syncthreads();
    for (int d = 1; d < SCAN_BLK; d <<= 1) {
        int t = (threadIdx.x >= d) ? s[threadIdx.x - d] : 0;
        __syncthreads();
        if (threadIdx.x >= d) s[threadIdx.x] += t;
        __syncthreads();
    }
    if (i < N_NODES) g_offsets[i] = s[threadIdx.x] - v;   // exclusive
    if (threadIdx.x == SCAN_BLK - 1) g_blocksums[blockIdx.x] = s[SCAN_BLK - 1];
}

__global__ void scan_phase2(int nb) {
    __shared__ int s[256];
    int v = (threadIdx.x < nb) ? g_blocksums[threadIdx.x] : 0;
    s[threadIdx.x] = v;
    __syncthreads();
    for (int d = 1; d < 256; d <<= 1) {
        int t = (threadIdx.x >= d) ? s[threadIdx.x - d] : 0;
        __syncthreads();
        if (threadIdx.x >= d) s[threadIdx.x] += t;
        __syncthreads();
    }
    g_blocksums[threadIdx.x] = s[threadIdx.x] - v;        // exclusive
}

__global__ void scan_phase3() {
    int i = blockIdx.x * blockDim.x + threadIdx.x;
    if (i < N_NODES) g_offsets[i] += g_blocksums[i >> 10];
}

__global__ void invdeg_kernel() {
    int i = blockIdx.x * blockDim.x + threadIdx.x;
    if (i < N_NODES) g_invdeg[i] = 1.0f / fmaxf((float)g_count[i], 1.0f);
}

__global__ void fill_kernel(const int* __restrict__ src, const int* __restrict__ dst) {
    int e = blockIdx.x * blockDim.x + threadIdx.x;
    if (e < N_EDGES) g_adj[g_offsets[dst[e]] + g_pos[e]] = src[e];
}

// ---------------- fused SAGE layer (wide gather) ----------------
// One warp per dst node. Lane = (g, c): g = lane>>3 picks one of 4 neighbors
// processed simultaneously, c = lane&7 picks a float4 chunk of the 32-float row.
// Each warp LDG.128 pulls 4 full neighbor rows (4 x 128B lines); 8-chunk unroll
// keeps ~16-32 lines in flight. Cross-group butterfly reduction, then the
// 32x32 Ws/Wn matvec via shuffle broadcast with weights in shared.
__global__ __launch_bounds__(256) void layer_kernel(
        const float* __restrict__ hin, int stride,
        float* __restrict__ hout,              // concat + l*32, row stride 128
        const float* __restrict__ Ws,
        const float* __restrict__ Wn,
        const float* __restrict__ b) {
    __shared__ float sW[2 * 1024 + 32];
    int tid = threadIdx.x;
    for (int i = tid; i < 1024; i += blockDim.x) {
        sW[i] = Ws[i];
        sW[1024 + i] = Wn[i];
    }
    if (tid < 32) sW[2048 + tid] = b[tid];
    __syncthreads();

    const unsigned FULL = 0xffffffffu;
    int lane = tid & 31;
    int g = lane >> 3;    // neighbor-within-quad
    int c = lane & 7;     // float4 chunk (features 4c..4c+3)
    int node = blockIdx.x * (blockDim.x >> 5) + (tid >> 5);
    if (node >= N_NODES) return;

    int beg = g_offsets[node];
    int cnt = g_count[node];
    int end = beg + cnt;

    float4 acc0 = make_float4(0.f, 0.f, 0.f, 0.f);
    float4 acc1 = make_float4(0.f, 0.f, 0.f, 0.f);

    for (int base = beg; base < end; base += 32) {
        int a = (base + lane < end) ? g_adj[base + lane] : 0;
#pragma unroll
        for (int j = 0; j < 8; j++) {
            int nidx = j * 4 + g;
            int s = __shfl_sync(FULL, a, nidx);
            if (base + nidx < end) {
                float4 v = __ldg((const float4*)(hin + (size_t)s * stride) + c);
                if (j & 1) {
                    acc1.x += v.x; acc1.y += v.y; acc1.z += v.z; acc1.w += v.w;
                } else {
                    acc0.x += v.x; acc0.y += v.y; acc0.z += v.z; acc0.w += v.w;
                }
            }
        }
    }
    acc0.x += acc1.x; acc0.y += acc1.y; acc0.z += acc1.z; acc0.w += acc1.w;
    // reduce across the 4 neighbor groups (lanes differing in bits 3,4)
#pragma unroll
    for (int off = 8; off <= 16; off <<= 1) {
        acc0.x += __shfl_xor_sync(FULL, acc0.x, off);
        acc0.y += __shfl_xor_sync(FULL, acc0.y, off);
        acc0.z += __shfl_xor_sync(FULL, acc0.z, off);
        acc0.w += __shfl_xor_sync(FULL, acc0.w, off);
    }
    float inv = g_invdeg[node];
    float m4[4] = { acc0.x * inv, acc0.y * inv, acc0.z * inv, acc0.w * inv };
    // m4[k&3] on lane k>>2 holds mean feature k (replicated across groups)

    float hv = __ldg(&hin[(size_t)node * stride + lane]);

    float o = sW[2048 + lane];
#pragma unroll
    for (int k = 0; k < 32; k++) {
        float hk = __shfl_sync(FULL, hv, k);
        float mk = __shfl_sync(FULL, m4[k & 3], k >> 2);
        o += hk * sW[k * 32 + lane] + mk * sW[1024 + k * 32 + lane];
    }
    hout[(size_t)node * CONCAT + lane] = tanhf(o);
}

// ---------------- pair MLP ----------------
__global__ void mlp_kernel(const float* __restrict__ concat,
                           const int* __restrict__ user_idx,
                           const int* __restrict__ item_idx,
                           const float* __restrict__ W1,
                           const float* __restrict__ bl1,
                           const float* __restrict__ W2,
                           const float* __restrict__ bl2,
                           float* __restrict__ score) {
    const int PB = 32;
    __shared__ float sP[PB][256];
    __shared__ float sOut[PB];
    int tid = threadIdx.x;       // 0..127
    int p0  = blockIdx.x * PB;

    for (int idx = tid; idx < PB * 256; idx += 128) {
        int p = idx >> 8, k = idx & 255;
        int pair = p0 + p;
        int node = (k < 128) ? user_idx[pair] : item_idx[pair];
        sP[p][k] = concat[(size_t)node * 128 + (k & 127)];
    }
    if (tid < PB) sOut[tid] = 0.0f;
    __syncthreads();

    float acc[PB];
#pragma unroll
    for (int p = 0; p < PB; p++) acc[p] = 0.0f;

    for (int k = 0; k < 256; k++) {
        float w = W1[k * 128 + tid];
#pragma unroll
        for (int p = 0; p < PB; p++) acc[p] += sP[p][k] * w;
    }

    float bj = bl1[tid];
    float w2 = W2[tid];
#pragma unroll
    for (int p = 0; p < PB; p++) {
        float h = fmaxf(acc[p] + bj, 0.0f);
        atomicAdd(&sOut[p], h * w2);
    }
    __syncthreads();

    if (tid < PB) {
        float v = sOut[tid] + bl2[0];
        score[p0 + tid] = 1.0f / (1.0f + expf(-v));
    }
}

// ---------------- launch ----------------
extern "C" void kernel_launch(void* const* d_in, const int* in_sizes, int n_in,
                              void* d_out, int out_size) {
    const float* x        = (const float*)d_in[0];
    const int*   src      = (const int*)d_in[1];
    const int*   dst      = (const int*)d_in[2];
    const int*   user_idx = (const int*)d_in[3];
    const int*   item_idx = (const int*)d_in[4];
    const float* Ws[4]; const float* Wn[4]; const float* B[4];
    for (int l = 0; l < 4; l++) {
        Ws[l] = (const float*)d_in[5 + 3 * l];
        Wn[l] = (const float*)d_in[6 + 3 * l];
        B[l]  = (const float*)d_in[7 + 3 * l];
    }
    const float* W1  = (const float*)d_in[17];
    const float* bl1 = (const float*)d_in[18];
    const float* W2  = (const float*)d_in[19];
    const float* bl2 = (const float*)d_in[20];

    float* out    = (float*)d_out;
    float* score  = out;             // [N_PAIRS]
    float* concat = out + N_PAIRS;   // [N_NODES, 128]

    void* countPtr = nullptr;
    cudaGetSymbolAddress(&countPtr, g_count);
    cudaMemsetAsync(countPtr, 0, N_NODES * sizeof(int));

    hist_kernel<<<(N_EDGES + 255) / 256, 256>>>(dst);
    scan_phase1<<<NB_SCAN, SCAN_BLK>>>();
    scan_phase2<<<1, 256>>>(NB_SCAN);
    scan_phase3<<<(N_NODES + 255) / 256, 256>>>();
    invdeg_kernel<<<(N_NODES + 255) / 256, 256>>>();
    fill_kernel<<<(N_EDGES + 255) / 256, 256>>>(src, dst);

    const int WPB = 8;  // warps per block (256 threads)
    int lblocks = (N_NODES + WPB - 1) / WPB;
    layer_kernel<<<lblocks, 256>>>(x,            32,  concat + 0,  Ws[0], Wn[0], B[0]);
    layer_kernel<<<lblocks, 256>>>(concat + 0,   128, concat + 32, Ws[1], Wn[1], B[1]);
    layer_kernel<<<lblocks, 256>>>(concat + 32,  128, concat + 64, Ws[2], Wn[2], B[2]);
    layer_kernel<<<lblocks, 256>>>(concat + 64,  128, concat + 96, Ws[3], Wn[3], B[3]);

    mlp_kernel<<<N_PAIRS / 32, 128>>>(concat, user_idx, item_idx, W1, bl1, W2, bl2, score);
}